// round 1
// baseline (speedup 1.0000x reference)
#include <cuda_runtime.h>
#include <cuda_bf16.h>
#include <math.h>

// Problem constants
#define BATCH   32
#define S_NEW   8
#define S_CACHE 4096
#define S_TOT   4104            // 4096 + 8
#define DIM     1024
#define M_ROWS  (BATCH * S_NEW) // 256

// Scratch (allocation-free rule: __device__ globals)
__device__ float g_q[M_ROWS * DIM];            // 1 MB   q_new
__device__ float g_scores[M_ROWS * S_TOT];     // ~4.2 MB scores -> probs

// ---------------------------------------------------------------------------
// Kernel 1: projections. C[m][n] = x[m][:] . W[:][n] + b[n]
// grid (16, 4, 3): z selects Q/K/V. 64x64 tile, BK=16, 256 thr, 4x4 microtile.
// Q -> g_q. K/V new rows -> tails of keys/values output regions.
// ---------------------------------------------------------------------------
__global__ void proj_kernel(const float* __restrict__ x,
                            const float* __restrict__ Wq, const float* __restrict__ bq,
                            const float* __restrict__ Wk, const float* __restrict__ bk,
                            const float* __restrict__ Wv, const float* __restrict__ bv,
                            float* __restrict__ keys, float* __restrict__ values)
{
    const int z = blockIdx.z;
    const float* W    = (z == 0) ? Wq : (z == 1) ? Wk : Wv;
    const float* bias = (z == 0) ? bq : (z == 1) ? bk : bv;

    __shared__ float xs[64][17];
    __shared__ float ws[16][64];

    const int tid = threadIdx.x;
    const int tx = tid & 15, ty = tid >> 4;
    const int m0 = blockIdx.y * 64, n0 = blockIdx.x * 64;

    float acc[4][4] = {};

    for (int k0 = 0; k0 < DIM; k0 += 16) {
        {   // x tile 64x16
            int r = tid >> 2;
            int c = (tid & 3) * 4;
            float4 v = *(const float4*)(x + (size_t)(m0 + r) * DIM + k0 + c);
            xs[r][c] = v.x; xs[r][c + 1] = v.y; xs[r][c + 2] = v.z; xs[r][c + 3] = v.w;
        }
        {   // W tile 16x64
            int r = tid >> 4;
            int c = (tid & 15) * 4;
            *(float4*)&ws[r][c] = *(const float4*)(W + (size_t)(k0 + r) * DIM + n0 + c);
        }
        __syncthreads();
        #pragma unroll
        for (int kk = 0; kk < 16; kk++) {
            float a[4];
            #pragma unroll
            for (int i = 0; i < 4; i++) a[i] = xs[ty * 4 + i][kk];
            float4 bb = *(float4*)&ws[kk][tx * 4];
            #pragma unroll
            for (int i = 0; i < 4; i++) {
                acc[i][0] += a[i] * bb.x;
                acc[i][1] += a[i] * bb.y;
                acc[i][2] += a[i] * bb.z;
                acc[i][3] += a[i] * bb.w;
            }
        }
        __syncthreads();
    }

    #pragma unroll
    for (int i = 0; i < 4; i++) {
        int m = m0 + ty * 4 + i;
        #pragma unroll
        for (int j = 0; j < 4; j++) {
            int n = n0 + tx * 4 + j;
            float val = acc[i][j] + bias[n];
            if (z == 0) {
                g_q[(size_t)m * DIM + n] = val;
            } else {
                int b = m >> 3, s = m & 7;
                float* dst = (z == 1) ? keys : values;
                dst[(size_t)b * S_TOT * DIM + (size_t)(S_CACHE + s) * DIM + n] = val;
            }
        }
    }
}

// ---------------------------------------------------------------------------
// Kernel 2: fused key-cache copy + score computation.
// grid (ceil(S_TOT/128)=33, BATCH). 8 warps; warp handles keys s = c0+w, +8...
// Streams each key row once: copy cache->keys output AND dot with 8 queries.
// ---------------------------------------------------------------------------
__global__ void scores_kernel(const float* __restrict__ key_cache,
                              float* __restrict__ keys)
{
    const int b    = blockIdx.y;
    const int c0   = blockIdx.x * 128;
    const int tid  = threadIdx.x;
    const int warp = tid >> 5, lane = tid & 31;

    __shared__ float4 qs4[S_NEW * 256];   // 8 queries x 1024 floats = 32 KB
    {
        const float4* qsrc = (const float4*)(g_q + (size_t)b * S_NEW * DIM);
        for (int i = tid; i < S_NEW * 256; i += 256) qs4[i] = qsrc[i];
    }
    __syncthreads();

    const int send = (c0 + 128 < S_TOT) ? c0 + 128 : S_TOT;
    for (int s = c0 + warp; s < send; s += 8) {
        const bool from_cache = (s < S_CACHE);
        const float* krow = from_cache
            ? key_cache + ((size_t)b * S_CACHE + s) * DIM
            : keys      + ((size_t)b * S_TOT   + s) * DIM;
        float* kdst = keys + ((size_t)b * S_TOT + s) * DIM;

        float acc[S_NEW] = {};
        #pragma unroll
        for (int it = 0; it < 8; it++) {
            const int d = it * 128 + lane * 4;
            float4 kv = *(const float4*)(krow + d);
            if (from_cache) *(float4*)(kdst + d) = kv;
            #pragma unroll
            for (int q = 0; q < S_NEW; q++) {
                float4 qv = qs4[q * 256 + it * 32 + lane];
                acc[q] += kv.x * qv.x + kv.y * qv.y + kv.z * qv.z + kv.w * qv.w;
            }
        }
        #pragma unroll
        for (int q = 0; q < S_NEW; q++) {
            float v = acc[q];
            #pragma unroll
            for (int off = 16; off; off >>= 1)
                v += __shfl_down_sync(0xFFFFFFFFu, v, off);
            if (lane == 0)
                g_scores[((size_t)b * S_NEW + q) * S_TOT + s] = v * 0.03125f; // 1/sqrt(1024)
        }
    }
}

// ---------------------------------------------------------------------------
// Kernel 3: softmax over each score row (256 rows x 4104). In-place -> probs.
// ---------------------------------------------------------------------------
__global__ void softmax_kernel()
{
    float* p = g_scores + (size_t)blockIdx.x * S_TOT;
    const int tid = threadIdx.x;
    __shared__ float red[256];

    float m = -1e30f;
    for (int i = tid; i < S_TOT; i += 256) m = fmaxf(m, p[i]);
    red[tid] = m; __syncthreads();
    for (int s = 128; s; s >>= 1) {
        if (tid < s) red[tid] = fmaxf(red[tid], red[tid + s]);
        __syncthreads();
    }
    m = red[0];
    __syncthreads();

    float sum = 0.f;
    for (int i = tid; i < S_TOT; i += 256) {
        float e = __expf(p[i] - m);
        p[i] = e;
        sum += e;
    }
    red[tid] = sum; __syncthreads();
    for (int s = 128; s; s >>= 1) {
        if (tid < s) red[tid] += red[tid + s];
        __syncthreads();
    }
    const float inv = 1.0f / red[0];
    for (int i = tid; i < S_TOT; i += 256) p[i] *= inv;
}

// ---------------------------------------------------------------------------
// Kernel 4: fused value-cache copy + probs @ V.
// grid (DIM/128 = 8, BATCH). Block owns (batch b, 128 output columns).
// Streams each value row chunk once: copy cache->values output AND accumulate.
// ---------------------------------------------------------------------------
__global__ void out_kernel(const float* __restrict__ value_cache,
                           float* __restrict__ values,
                           float* __restrict__ out)
{
    const int b   = blockIdx.y;
    const int d0  = blockIdx.x * 128;
    const int tid = threadIdx.x;
    const int warp = tid >> 5, lane = tid & 31;

    __shared__ float accsm[S_NEW][128];
    for (int i = tid; i < S_NEW * 128; i += 256) ((float*)accsm)[i] = 0.f;
    __syncthreads();

    float acc[S_NEW][4] = {};
    const float* probs = g_scores + (size_t)b * S_NEW * S_TOT;

    for (int s = warp; s < S_TOT; s += 8) {
        const bool from_cache = (s < S_CACHE);
        const float* vrow = from_cache
            ? value_cache + ((size_t)b * S_CACHE + s) * DIM
            : values      + ((size_t)b * S_TOT   + s) * DIM;
        float4 vv = *(const float4*)(vrow + d0 + lane * 4);
        if (from_cache)
            *(float4*)(values + ((size_t)b * S_TOT + s) * DIM + d0 + lane * 4) = vv;
        #pragma unroll
        for (int q = 0; q < S_NEW; q++) {
            float pq = probs[(size_t)q * S_TOT + s];
            acc[q][0] += pq * vv.x;
            acc[q][1] += pq * vv.y;
            acc[q][2] += pq * vv.z;
            acc[q][3] += pq * vv.w;
        }
    }

    #pragma unroll
    for (int q = 0; q < S_NEW; q++) {
        #pragma unroll
        for (int j = 0; j < 4; j++)
            atomicAdd(&accsm[q][lane * 4 + j], acc[q][j]);
    }
    __syncthreads();

    for (int i = tid; i < S_NEW * 128; i += 256) {
        int q = i >> 7, c = i & 127;
        out[(size_t)b * S_NEW * DIM + (size_t)q * DIM + d0 + c] = accsm[q][c];
    }
}

// ---------------------------------------------------------------------------
extern "C" void kernel_launch(void* const* d_in, const int* in_sizes, int n_in,
                              void* d_out, int out_size)
{
    const float* input       = (const float*)d_in[0];
    const float* key_cache   = (const float*)d_in[1];
    const float* value_cache = (const float*)d_in[2];
    const float* Wk          = (const float*)d_in[3];
    const float* bk          = (const float*)d_in[4];
    const float* Wv          = (const float*)d_in[5];
    const float* bv          = (const float*)d_in[6];
    const float* Wq          = (const float*)d_in[7];
    const float* bq          = (const float*)d_in[8];

    float* out    = (float*)d_out;                                // [B, S_NEW, D]
    float* keys   = out + (size_t)BATCH * S_NEW * DIM;            // [B, S_TOT, D]
    float* values = keys + (size_t)BATCH * S_TOT * DIM;           // [B, S_TOT, D]

    // 1) projections: q -> scratch, k/v new rows -> output tails
    proj_kernel<<<dim3(16, 4, 3), 256>>>(input, Wq, bq, Wk, bk, Wv, bv, keys, values);

    // 2) fused key copy + scores
    scores_kernel<<<dim3((S_TOT + 127) / 128, BATCH), 256>>>(key_cache, keys);

    // 3) softmax
    softmax_kernel<<<M_ROWS, 256>>>();

    // 4) fused value copy + probs @ V
    out_kernel<<<dim3(DIM / 128, BATCH), 256>>>(value_cache, values, out);
}

// round 3
// speedup vs baseline: 1.6600x; 1.6600x over previous
#include <cuda_runtime.h>
#include <cuda_bf16.h>
#include <math.h>

// Problem constants
#define BATCH   32
#define S_NEW   8
#define S_CACHE 4096
#define S_TOT   4104            // 4096 + 8
#define DIM     1024
#define M_ROWS  (BATCH * S_NEW) // 256
#define SPLITS  16
#define CHUNK   ((S_TOT + SPLITS - 1) / SPLITS)   // 257
#define NSLICE  (2 * SPLITS)                      // 32 partial slices

// Scratch (allocation-free rule: __device__ globals)
__device__ float g_q[M_ROWS * DIM];                 // 1 MB   q_new
__device__ float g_scores[M_ROWS * S_TOT];          // ~4.2 MB scores -> probs
__device__ float g_part[NSLICE * M_ROWS * DIM];     // 32 MB  split-K partials

// ---------------------------------------------------------------------------
// Kernel 1: projections. C[m][n] = x[m][:] . W[:][n] + b[n]
// grid (16, 4, 3): z selects Q/K/V. 64x64 tile, BK=16, 256 thr, 4x4 microtile.
// Q -> g_q. K/V new rows -> tails of keys/values output regions.
// ---------------------------------------------------------------------------
__global__ void proj_kernel(const float* __restrict__ x,
                            const float* __restrict__ Wq, const float* __restrict__ bq,
                            const float* __restrict__ Wk, const float* __restrict__ bk,
                            const float* __restrict__ Wv, const float* __restrict__ bv,
                            float* __restrict__ keys, float* __restrict__ values)
{
    const int z = blockIdx.z;
    const float* W    = (z == 0) ? Wq : (z == 1) ? Wk : Wv;
    const float* bias = (z == 0) ? bq : (z == 1) ? bk : bv;

    __shared__ float xs[64][17];
    __shared__ float ws[16][64];

    const int tid = threadIdx.x;
    const int tx = tid & 15, ty = tid >> 4;
    const int m0 = blockIdx.y * 64, n0 = blockIdx.x * 64;

    float acc[4][4] = {};

    for (int k0 = 0; k0 < DIM; k0 += 16) {
        {   // x tile 64x16
            int r = tid >> 2;
            int c = (tid & 3) * 4;
            float4 v = *(const float4*)(x + (size_t)(m0 + r) * DIM + k0 + c);
            xs[r][c] = v.x; xs[r][c + 1] = v.y; xs[r][c + 2] = v.z; xs[r][c + 3] = v.w;
        }
        {   // W tile 16x64
            int r = tid >> 4;
            int c = (tid & 15) * 4;
            *(float4*)&ws[r][c] = *(const float4*)(W + (size_t)(k0 + r) * DIM + n0 + c);
        }
        __syncthreads();
        #pragma unroll
        for (int kk = 0; kk < 16; kk++) {
            float a[4];
            #pragma unroll
            for (int i = 0; i < 4; i++) a[i] = xs[ty * 4 + i][kk];
            float4 bb = *(float4*)&ws[kk][tx * 4];
            #pragma unroll
            for (int i = 0; i < 4; i++) {
                acc[i][0] += a[i] * bb.x;
                acc[i][1] += a[i] * bb.y;
                acc[i][2] += a[i] * bb.z;
                acc[i][3] += a[i] * bb.w;
            }
        }
        __syncthreads();
    }

    #pragma unroll
    for (int i = 0; i < 4; i++) {
        int m = m0 + ty * 4 + i;
        #pragma unroll
        for (int j = 0; j < 4; j++) {
            int n = n0 + tx * 4 + j;
            float val = acc[i][j] + bias[n];
            if (z == 0) {
                g_q[(size_t)m * DIM + n] = val;
            } else {
                int b = m >> 3, s = m & 7;
                float* dst = (z == 1) ? keys : values;
                dst[(size_t)b * S_TOT * DIM + (size_t)(S_CACHE + s) * DIM + n] = val;
            }
        }
    }
}

// ---------------------------------------------------------------------------
// Kernel 2: fused key-cache copy + score computation.
// grid (ceil(S_TOT/64), BATCH). 8 warps; each warp handles 8 key rows.
// Streams each key row once: copy cache->keys output AND dot with 8 queries.
// ---------------------------------------------------------------------------
__global__ void scores_kernel(const float* __restrict__ key_cache,
                              float* __restrict__ keys)
{
    const int b    = blockIdx.y;
    const int c0   = blockIdx.x * 64;
    const int tid  = threadIdx.x;
    const int warp = tid >> 5, lane = tid & 31;

    __shared__ float4 qs4[S_NEW * 256];   // 8 queries x 1024 floats = 32 KB
    {
        const float4* qsrc = (const float4*)(g_q + (size_t)b * S_NEW * DIM);
        for (int i = tid; i < S_NEW * 256; i += 256) qs4[i] = qsrc[i];
    }
    __syncthreads();

    const int send = (c0 + 64 < S_TOT) ? c0 + 64 : S_TOT;
    for (int s = c0 + warp; s < send; s += 8) {
        const bool from_cache = (s < S_CACHE);
        const float* krow = from_cache
            ? key_cache + ((size_t)b * S_CACHE + s) * DIM
            : keys      + ((size_t)b * S_TOT   + s) * DIM;
        float* kdst = keys + ((size_t)b * S_TOT + s) * DIM;

        float acc[S_NEW] = {};
        #pragma unroll
        for (int it = 0; it < 8; it++) {
            const int d = it * 128 + lane * 4;
            float4 kv = *(const float4*)(krow + d);
            if (from_cache) *(float4*)(kdst + d) = kv;
            #pragma unroll
            for (int q = 0; q < S_NEW; q++) {
                float4 qv = qs4[q * 256 + it * 32 + lane];
                acc[q] += kv.x * qv.x + kv.y * qv.y + kv.z * qv.z + kv.w * qv.w;
            }
        }
        #pragma unroll
        for (int q = 0; q < S_NEW; q++) {
            float v = acc[q];
            #pragma unroll
            for (int off = 16; off; off >>= 1)
                v += __shfl_down_sync(0xFFFFFFFFu, v, off);
            if (lane == 0)
                g_scores[((size_t)b * S_NEW + q) * S_TOT + s] = v * 0.03125f; // 1/sqrt(1024)
        }
    }
}

// ---------------------------------------------------------------------------
// Kernel 3: softmax over each score row (256 rows x 4104). In-place -> probs.
// ---------------------------------------------------------------------------
__global__ void softmax_kernel()
{
    float* p = g_scores + (size_t)blockIdx.x * S_TOT;
    const int tid = threadIdx.x;
    __shared__ float red[256];

    float m = -1e30f;
    for (int i = tid; i < S_TOT; i += 256) m = fmaxf(m, p[i]);
    red[tid] = m; __syncthreads();
    for (int s = 128; s; s >>= 1) {
        if (tid < s) red[tid] = fmaxf(red[tid], red[tid + s]);
        __syncthreads();
    }
    m = red[0];
    __syncthreads();

    float sum = 0.f;
    for (int i = tid; i < S_TOT; i += 256) {
        float e = __expf(p[i] - m);
        p[i] = e;
        sum += e;
    }
    red[tid] = sum; __syncthreads();
    for (int s = 128; s; s >>= 1) {
        if (tid < s) red[tid] += red[tid + s];
        __syncthreads();
    }
    const float inv = 1.0f / red[0];
    for (int i = tid; i < S_TOT; i += 256) p[i] *= inv;
}

// ---------------------------------------------------------------------------
// Kernel 4: fused value-cache copy + split-K probs @ V.
// grid (BATCH, SPLITS), 512 threads. Threads split into 2 row-groups of 256;
// group g covers rows s_beg+g, s_beg+g+2, ... Each of the 256 column-threads
// owns 4 output columns (256*4 = 1024 = DIM, all columns, no overlap).
// Streams each value row once: copy cache->values output AND accumulate.
// Partials go to slice (z*2+g) of g_part; combined by combine_kernel.
// ---------------------------------------------------------------------------
__global__ void __launch_bounds__(512)
out_kernel(const float* __restrict__ value_cache,
           float* __restrict__ values)
{
    const int b    = blockIdx.x;
    const int z    = blockIdx.y;            // split index
    const int tid  = threadIdx.x;
    const int grp  = tid >> 8;               // 0 or 1 (row group)
    const int col  = (tid & 255) * 4;        // this thread's 4 columns

    const int s_beg = z * CHUNK;
    const int s_end = (s_beg + CHUNK < S_TOT) ? s_beg + CHUNK : S_TOT;
    const int s_mid = (s_end < S_CACHE) ? s_end : ((s_beg > S_CACHE) ? s_beg : S_CACHE);

    // probs chunk for this (batch, split): 8 x CHUNK floats (~8.2 KB)
    __shared__ float ps[S_NEW][CHUNK];
    {
        const float* probs = g_scores + (size_t)b * S_NEW * S_TOT;
        const int n = s_end - s_beg;
        for (int i = tid; i < S_NEW * n; i += 512) {
            int q = i / n, s = i - q * n;
            ps[q][s] = probs[(size_t)q * S_TOT + s_beg + s];
        }
    }
    __syncthreads();

    float acc[S_NEW][4] = {};

    const float* vsrc = value_cache + (size_t)b * S_CACHE * DIM + col;
    float*       vdst = values      + (size_t)b * S_TOT   * DIM + col;

    // cache region: stream + copy + accumulate (rows s_beg+grp, step 2)
    #pragma unroll 2
    for (int s = s_beg + grp; s < s_mid; s += 2) {
        float4 vv = *(const float4*)(vsrc + (size_t)s * DIM);
        *(float4*)(vdst + (size_t)s * DIM) = vv;
        #pragma unroll
        for (int q = 0; q < S_NEW; q++) {
            float pq = ps[q][s - s_beg];
            acc[q][0] += pq * vv.x;
            acc[q][1] += pq * vv.y;
            acc[q][2] += pq * vv.z;
            acc[q][3] += pq * vv.w;
        }
    }
    // tail region (new rows already in values, written by proj_kernel)
    for (int s = (s_mid > s_beg + grp ? (s_mid + ((s_mid - s_beg - grp) & 1 ? 1 : 0)) : s_beg + grp);
         s < s_end; s += 2) {
        // recompute correct parity start for this group within [s_mid, s_end)
        break;
    }
    {   // simple tail handling: iterate all tail rows of this group's parity
        for (int s = s_mid; s < s_end; s++) {
            if (((s - s_beg) & 1) != grp) continue;
            float4 vv = *(const float4*)(vdst + (size_t)s * DIM);
            #pragma unroll
            for (int q = 0; q < S_NEW; q++) {
                float pq = ps[q][s - s_beg];
                acc[q][0] += pq * vv.x;
                acc[q][1] += pq * vv.y;
                acc[q][2] += pq * vv.z;
                acc[q][3] += pq * vv.w;
            }
        }
    }

    // write partials: slice (z*2+grp)
    float* pbase = g_part + (size_t)(z * 2 + grp) * M_ROWS * DIM
                          + (size_t)b * S_NEW * DIM + col;
    #pragma unroll
    for (int q = 0; q < S_NEW; q++)
        *(float4*)(pbase + (size_t)q * DIM) = *(float4*)acc[q];
}

// ---------------------------------------------------------------------------
// Kernel 5: deterministic split-K combine. out[m][d] = sum_z g_part[z][m][d].
// ---------------------------------------------------------------------------
__global__ void combine_kernel(float* __restrict__ out)
{
    const int idx = blockIdx.x * blockDim.x + threadIdx.x;   // float4 index
    const float4* p = (const float4*)g_part + idx;
    float4 a = {0.f, 0.f, 0.f, 0.f};
    #pragma unroll
    for (int z = 0; z < NSLICE; z++) {
        float4 v = p[(size_t)z * (M_ROWS * DIM / 4)];
        a.x += v.x; a.y += v.y; a.z += v.z; a.w += v.w;
    }
    ((float4*)out)[idx] = a;
}

// ---------------------------------------------------------------------------
extern "C" void kernel_launch(void* const* d_in, const int* in_sizes, int n_in,
                              void* d_out, int out_size)
{
    const float* input       = (const float*)d_in[0];
    const float* key_cache   = (const float*)d_in[1];
    const float* value_cache = (const float*)d_in[2];
    const float* Wk          = (const float*)d_in[3];
    const float* bk          = (const float*)d_in[4];
    const float* Wv          = (const float*)d_in[5];
    const float* bv          = (const float*)d_in[6];
    const float* Wq          = (const float*)d_in[7];
    const float* bq          = (const float*)d_in[8];

    float* out    = (float*)d_out;                                // [B, S_NEW, D]
    float* keys   = out + (size_t)BATCH * S_NEW * DIM;            // [B, S_TOT, D]
    float* values = keys + (size_t)BATCH * S_TOT * DIM;           // [B, S_TOT, D]

    // 1) projections: q -> scratch, k/v new rows -> output tails
    proj_kernel<<<dim3(16, 4, 3), 256>>>(input, Wq, bq, Wk, bk, Wv, bv, keys, values);

    // 2) fused key copy + scores
    scores_kernel<<<dim3((S_TOT + 63) / 64, BATCH), 256>>>(key_cache, keys);

    // 3) softmax
    softmax_kernel<<<M_ROWS, 256>>>();

    // 4) fused value copy + split-K probs @ V
    out_kernel<<<dim3(BATCH, SPLITS), 512>>>(value_cache, values);

    // 5) deterministic combine of split-K partials
    combine_kernel<<<(M_ROWS * DIM / 4) / 256, 256>>>(out);
}

// round 4
// speedup vs baseline: 1.6640x; 1.0024x over previous
#include <cuda_runtime.h>
#include <cuda_bf16.h>
#include <math.h>

// Problem constants
#define BATCH   32
#define S_NEW   8
#define S_CACHE 4096
#define S_TOT   4104            // 4096 + 8
#define DIM     1024
#define M_ROWS  (BATCH * S_NEW) // 256
#define SPLITS  16
#define CHUNK   ((S_TOT + SPLITS - 1) / SPLITS)   // 257
#define NSLICE  (2 * SPLITS)                      // 32 partial slices

// Scratch (allocation-free rule: __device__ globals)
__device__ float g_q[M_ROWS * DIM];                 // 1 MB   q_new
__device__ float g_scores[M_ROWS * S_TOT];          // ~4.2 MB scores -> probs
__device__ float g_part[NSLICE * M_ROWS * DIM];     // 32 MB  split-K partials

// ---------------------------------------------------------------------------
// Kernel 1: projections. C[m][n] = x[m][:] . W[:][n] + b[n]
// grid (16, 4, 3): z selects Q/K/V. 64x64 tile, BK=16, 256 thr, 4x4 microtile.
// Q -> g_q. K/V new rows -> tails of keys/values output regions.
// ---------------------------------------------------------------------------
__global__ void proj_kernel(const float* __restrict__ x,
                            const float* __restrict__ Wq, const float* __restrict__ bq,
                            const float* __restrict__ Wk, const float* __restrict__ bk,
                            const float* __restrict__ Wv, const float* __restrict__ bv,
                            float* __restrict__ keys, float* __restrict__ values)
{
    const int z = blockIdx.z;
    const float* W    = (z == 0) ? Wq : (z == 1) ? Wk : Wv;
    const float* bias = (z == 0) ? bq : (z == 1) ? bk : bv;

    __shared__ float xs[64][17];
    __shared__ float ws[16][64];

    const int tid = threadIdx.x;
    const int tx = tid & 15, ty = tid >> 4;
    const int m0 = blockIdx.y * 64, n0 = blockIdx.x * 64;

    float acc[4][4] = {};

    for (int k0 = 0; k0 < DIM; k0 += 16) {
        {   // x tile 64x16
            int r = tid >> 2;
            int c = (tid & 3) * 4;
            float4 v = *(const float4*)(x + (size_t)(m0 + r) * DIM + k0 + c);
            xs[r][c] = v.x; xs[r][c + 1] = v.y; xs[r][c + 2] = v.z; xs[r][c + 3] = v.w;
        }
        {   // W tile 16x64
            int r = tid >> 4;
            int c = (tid & 15) * 4;
            *(float4*)&ws[r][c] = *(const float4*)(W + (size_t)(k0 + r) * DIM + n0 + c);
        }
        __syncthreads();
        #pragma unroll
        for (int kk = 0; kk < 16; kk++) {
            float a[4];
            #pragma unroll
            for (int i = 0; i < 4; i++) a[i] = xs[ty * 4 + i][kk];
            float4 bb = *(float4*)&ws[kk][tx * 4];
            #pragma unroll
            for (int i = 0; i < 4; i++) {
                acc[i][0] += a[i] * bb.x;
                acc[i][1] += a[i] * bb.y;
                acc[i][2] += a[i] * bb.z;
                acc[i][3] += a[i] * bb.w;
            }
        }
        __syncthreads();
    }

    #pragma unroll
    for (int i = 0; i < 4; i++) {
        int m = m0 + ty * 4 + i;
        #pragma unroll
        for (int j = 0; j < 4; j++) {
            int n = n0 + tx * 4 + j;
            float val = acc[i][j] + bias[n];
            if (z == 0) {
                g_q[(size_t)m * DIM + n] = val;
            } else {
                int b = m >> 3, s = m & 7;
                float* dst = (z == 1) ? keys : values;
                dst[(size_t)b * S_TOT * DIM + (size_t)(S_CACHE + s) * DIM + n] = val;
            }
        }
    }
}

// ---------------------------------------------------------------------------
// Kernel 2: fused key-cache copy + score computation.
// grid (ceil(S_TOT/64), BATCH). 8 warps; each warp handles 8 key rows.
// Streams each key row once: copy cache->keys output AND dot with 8 queries.
// ---------------------------------------------------------------------------
__global__ void scores_kernel(const float* __restrict__ key_cache,
                              float* __restrict__ keys)
{
    const int b    = blockIdx.y;
    const int c0   = blockIdx.x * 64;
    const int tid  = threadIdx.x;
    const int warp = tid >> 5, lane = tid & 31;

    __shared__ float4 qs4[S_NEW * 256];   // 8 queries x 1024 floats = 32 KB
    {
        const float4* qsrc = (const float4*)(g_q + (size_t)b * S_NEW * DIM);
        for (int i = tid; i < S_NEW * 256; i += 256) qs4[i] = qsrc[i];
    }
    __syncthreads();

    const int send = (c0 + 64 < S_TOT) ? c0 + 64 : S_TOT;
    for (int s = c0 + warp; s < send; s += 8) {
        const bool from_cache = (s < S_CACHE);
        const float* krow = from_cache
            ? key_cache + ((size_t)b * S_CACHE + s) * DIM
            : keys      + ((size_t)b * S_TOT   + s) * DIM;
        float* kdst = keys + ((size_t)b * S_TOT + s) * DIM;

        float acc[S_NEW] = {};
        #pragma unroll
        for (int it = 0; it < 8; it++) {
            const int d = it * 128 + lane * 4;
            float4 kv = *(const float4*)(krow + d);
            if (from_cache) *(float4*)(kdst + d) = kv;
            #pragma unroll
            for (int q = 0; q < S_NEW; q++) {
                float4 qv = qs4[q * 256 + it * 32 + lane];
                acc[q] += kv.x * qv.x + kv.y * qv.y + kv.z * qv.z + kv.w * qv.w;
            }
        }
        #pragma unroll
        for (int q = 0; q < S_NEW; q++) {
            float v = acc[q];
            #pragma unroll
            for (int off = 16; off; off >>= 1)
                v += __shfl_down_sync(0xFFFFFFFFu, v, off);
            if (lane == 0)
                g_scores[((size_t)b * S_NEW + q) * S_TOT + s] = v * 0.03125f; // 1/sqrt(1024)
        }
    }
}

// ---------------------------------------------------------------------------
// Kernel 3: softmax over each score row (256 rows x 4104). In-place -> probs.
// ---------------------------------------------------------------------------
__global__ void softmax_kernel()
{
    float* p = g_scores + (size_t)blockIdx.x * S_TOT;
    const int tid = threadIdx.x;
    __shared__ float red[256];

    float m = -1e30f;
    for (int i = tid; i < S_TOT; i += 256) m = fmaxf(m, p[i]);
    red[tid] = m; __syncthreads();
    for (int s = 128; s; s >>= 1) {
        if (tid < s) red[tid] = fmaxf(red[tid], red[tid + s]);
        __syncthreads();
    }
    m = red[0];
    __syncthreads();

    float sum = 0.f;
    for (int i = tid; i < S_TOT; i += 256) {
        float e = __expf(p[i] - m);
        p[i] = e;
        sum += e;
    }
    red[tid] = sum; __syncthreads();
    for (int s = 128; s; s >>= 1) {
        if (tid < s) red[tid] += red[tid + s];
        __syncthreads();
    }
    const float inv = 1.0f / red[0];
    for (int i = tid; i < S_TOT; i += 256) p[i] *= inv;
}

// ---------------------------------------------------------------------------
// Kernel 4: fused value-cache copy + split-K probs @ V.
// grid (BATCH, SPLITS), 512 threads. Threads split into 2 row-groups of 256;
// group g covers rows s_beg+g, s_beg+g+2, ... Each of the 256 column-threads
// owns 4 output columns (256*4 = 1024 = DIM, all columns, no overlap).
// Streams each value row once: copy cache->values output AND accumulate.
// Partials go to slice (z*2+g) of g_part; combined by combine_kernel.
// ---------------------------------------------------------------------------
__global__ void __launch_bounds__(512)
out_kernel(const float* __restrict__ value_cache,
           float* __restrict__ values)
{
    const int b    = blockIdx.x;
    const int z    = blockIdx.y;            // split index
    const int tid  = threadIdx.x;
    const int grp  = tid >> 8;               // 0 or 1 (row group)
    const int col  = (tid & 255) * 4;        // this thread's 4 columns

    const int s_beg = z * CHUNK;
    const int s_end = (s_beg + CHUNK < S_TOT) ? s_beg + CHUNK : S_TOT;
    const int s_mid = (s_end < S_CACHE) ? s_end : ((s_beg > S_CACHE) ? s_beg : S_CACHE);

    // probs chunk for this (batch, split): 8 x CHUNK floats (~8.2 KB)
    __shared__ float ps[S_NEW][CHUNK];
    {
        const float* probs = g_scores + (size_t)b * S_NEW * S_TOT;
        const int n = s_end - s_beg;
        for (int i = tid; i < S_NEW * n; i += 512) {
            int q = i / n, s = i - q * n;
            ps[q][s] = probs[(size_t)q * S_TOT + s_beg + s];
        }
    }
    __syncthreads();

    float acc[S_NEW][4] = {};

    const float* vsrc = value_cache + (size_t)b * S_CACHE * DIM + col;
    float*       vdst = values      + (size_t)b * S_TOT   * DIM + col;

    // cache region: stream + copy + accumulate (rows s_beg+grp, step 2)
    #pragma unroll 2
    for (int s = s_beg + grp; s < s_mid; s += 2) {
        float4 vv = *(const float4*)(vsrc + (size_t)s * DIM);
        *(float4*)(vdst + (size_t)s * DIM) = vv;
        #pragma unroll
        for (int q = 0; q < S_NEW; q++) {
            float pq = ps[q][s - s_beg];
            acc[q][0] += pq * vv.x;
            acc[q][1] += pq * vv.y;
            acc[q][2] += pq * vv.z;
            acc[q][3] += pq * vv.w;
        }
    }
    // tail region (new rows already in values, written by proj_kernel)
    for (int s = (s_mid > s_beg + grp ? (s_mid + ((s_mid - s_beg - grp) & 1 ? 1 : 0)) : s_beg + grp);
         s < s_end; s += 2) {
        // recompute correct parity start for this group within [s_mid, s_end)
        break;
    }
    {   // simple tail handling: iterate all tail rows of this group's parity
        for (int s = s_mid; s < s_end; s++) {
            if (((s - s_beg) & 1) != grp) continue;
            float4 vv = *(const float4*)(vdst + (size_t)s * DIM);
            #pragma unroll
            for (int q = 0; q < S_NEW; q++) {
                float pq = ps[q][s - s_beg];
                acc[q][0] += pq * vv.x;
                acc[q][1] += pq * vv.y;
                acc[q][2] += pq * vv.z;
                acc[q][3] += pq * vv.w;
            }
        }
    }

    // write partials: slice (z*2+grp)
    float* pbase = g_part + (size_t)(z * 2 + grp) * M_ROWS * DIM
                          + (size_t)b * S_NEW * DIM + col;
    #pragma unroll
    for (int q = 0; q < S_NEW; q++)
        *(float4*)(pbase + (size_t)q * DIM) = *(float4*)acc[q];
}

// ---------------------------------------------------------------------------
// Kernel 5: deterministic split-K combine. out[m][d] = sum_z g_part[z][m][d].
// ---------------------------------------------------------------------------
__global__ void combine_kernel(float* __restrict__ out)
{
    const int idx = blockIdx.x * blockDim.x + threadIdx.x;   // float4 index
    const float4* p = (const float4*)g_part + idx;
    float4 a = {0.f, 0.f, 0.f, 0.f};
    #pragma unroll
    for (int z = 0; z < NSLICE; z++) {
        float4 v = p[(size_t)z * (M_ROWS * DIM / 4)];
        a.x += v.x; a.y += v.y; a.z += v.z; a.w += v.w;
    }
    ((float4*)out)[idx] = a;
}

// ---------------------------------------------------------------------------
extern "C" void kernel_launch(void* const* d_in, const int* in_sizes, int n_in,
                              void* d_out, int out_size)
{
    const float* input       = (const float*)d_in[0];
    const float* key_cache   = (const float*)d_in[1];
    const float* value_cache = (const float*)d_in[2];
    const float* Wk          = (const float*)d_in[3];
    const float* bk          = (const float*)d_in[4];
    const float* Wv          = (const float*)d_in[5];
    const float* bv          = (const float*)d_in[6];
    const float* Wq          = (const float*)d_in[7];
    const float* bq          = (const float*)d_in[8];

    float* out    = (float*)d_out;                                // [B, S_NEW, D]
    float* keys   = out + (size_t)BATCH * S_NEW * DIM;            // [B, S_TOT, D]
    float* values = keys + (size_t)BATCH * S_TOT * DIM;           // [B, S_TOT, D]

    // 1) projections: q -> scratch, k/v new rows -> output tails
    proj_kernel<<<dim3(16, 4, 3), 256>>>(input, Wq, bq, Wk, bk, Wv, bv, keys, values);

    // 2) fused key copy + scores
    scores_kernel<<<dim3((S_TOT + 63) / 64, BATCH), 256>>>(key_cache, keys);

    // 3) softmax
    softmax_kernel<<<M_ROWS, 256>>>();

    // 4) fused value copy + split-K probs @ V
    out_kernel<<<dim3(BATCH, SPLITS), 512>>>(value_cache, values);

    // 5) deterministic combine of split-K partials
    combine_kernel<<<(M_ROWS * DIM / 4) / 256, 256>>>(out);
}